// round 5
// baseline (speedup 1.0000x reference)
#include <cuda_runtime.h>

#define BSZ  4
#define CH   128
#define HID  256
#define OUTD 64
#define EPSV 1e-5f
#define ALLM 0xffffffffu

// per-level phase2 partials: [5][8 chunks][256 = b*64+o]
__device__ float g_part[5 * 8 * 256];
// per-level arrival counters (zero-init at load; reset by last arriver)
__device__ int g_cnt[5];

__device__ __forceinline__ int atom_add_acqrel(int* p, int v)
{
    int old;
    asm volatile("atom.add.acq_rel.gpu.global.s32 %0, [%1], %2;"
                 : "=r"(old) : "l"(p), "r"(v) : "memory");
    return old;
}

// ---------------------------------------------------------------------------
// Fused kernel, 40 blocks (k = bx>>3, chunk = bx&7), 256 threads.
// Phase1: gather + Conv1 + BN + ReLU for this block's 32 hidden units (smem).
// Phase2-partial: each thread one (o,b), 32-MAC dot over OWN 32 channels.
// Last arriving block per level reduces the 8 partials and writes out.
// ---------------------------------------------------------------------------
__global__ __launch_bounds__(256, 1)
void proj_fused_kernel(const float* __restrict__ x0,
                       const float* __restrict__ x1,
                       const float* __restrict__ x2,
                       const float* __restrict__ x3,
                       const float* __restrict__ x4,
                       const int*   __restrict__ p,
                       const float* __restrict__ w1,
                       const float* __restrict__ b1,
                       const float* __restrict__ gamma,
                       const float* __restrict__ beta,
                       const float* __restrict__ w2,
                       const float* __restrict__ b2,
                       float*       __restrict__ out)
{
    const int k   = blockIdx.x >> 3;       // level 0..4
    const int ch8 = blockIdx.x & 7;        // 32-unit chunk within level
    const int t   = threadIdx.x;
    const int s   = t & 7;                 // interleaved float4 slot
    const int jloc = t >> 3;               // 0..31
    const int j   = ch8 * 32 + jloc;       // hidden unit (phase1)

    __shared__ float f_s[BSZ][CH];         // gathered features
    __shared__ float r_s[BSZ][32];         // this block's post-ReLU units
    __shared__ int   last_s;

    // ---- prefetch everything independent of the gather chain ----
    const float4* wrow = (const float4*)(w1 + ((long long)k * HID + j) * CH);
    float4 wv[4];
    #pragma unroll
    for (int i = 0; i < 4; ++i)
        wv[i] = wrow[s + 8 * i];

    const float bias = b1[k * HID + j];
    const float gam  = gamma[k * HID + j];
    const float bet  = beta[k * HID + j];

    // phase2-partial assignment: o = t>>2 (4-lane dedup on w2 row), b = t&3
    const int o2 = t >> 2;
    const int b2i = t & 3;
    const float4* w2row =
        (const float4*)(w2 + ((long long)k * OUTD + o2) * HID + ch8 * 32);
    float4 wv2[8];
    #pragma unroll
    for (int i = 0; i < 8; ++i)
        wv2[i] = w2row[i];
    const float bias2 = b2[k * OUTD + (t & 63)];   // for last-arriver path (u = t)

    // ---- gather 512 scattered floats (2 per thread) ----
    const float* xs;
    switch (k) {
        case 0: xs = x0; break;
        case 1: xs = x1; break;
        case 2: xs = x2; break;
        case 3: xs = x3; break;
        default: xs = x4; break;
    }
    const int shift = k + 1;
    const int side  = 128 >> shift;

    #pragma unroll
    for (int i = t; i < BSZ * CH; i += 256) {
        const int b = i >> 7;
        const int c = i & (CH - 1);
        const int q0 = p[b * 3 + 0] >> shift;
        const int q1 = p[b * 3 + 1] >> shift;
        const int q2 = p[b * 3 + 2] >> shift;
        const long long idx =
            ((((long long)(b * CH + c) * side + q0) * side + q1) * side + q2);
        f_s[b][c] = xs[idx];
    }
    __syncthreads();

    // ---- Conv1 partial dots (16 channels x 4 batches per thread) ----
    const float4* f0 = (const float4*)f_s[0];
    const float4* f1 = (const float4*)f_s[1];
    const float4* f2 = (const float4*)f_s[2];
    const float4* f3 = (const float4*)f_s[3];

    float a0 = 0.f, a1 = 0.f, a2 = 0.f, a3 = 0.f;
    #pragma unroll
    for (int i = 0; i < 4; ++i) {
        const int fi = s + 8 * i;
        const float4 w = wv[i];
        float4 v;
        v = f0[fi]; a0 += v.x*w.x + v.y*w.y + v.z*w.z + v.w*w.w;
        v = f1[fi]; a1 += v.x*w.x + v.y*w.y + v.z*w.z + v.w*w.w;
        v = f2[fi]; a2 += v.x*w.x + v.y*w.y + v.z*w.z + v.w*w.w;
        v = f3[fi]; a3 += v.x*w.x + v.y*w.y + v.z*w.z + v.w*w.w;
    }
    #pragma unroll
    for (int m = 1; m < 8; m <<= 1) {
        a0 += __shfl_xor_sync(ALLM, a0, m);
        a1 += __shfl_xor_sync(ALLM, a1, m);
        a2 += __shfl_xor_sync(ALLM, a2, m);
        a3 += __shfl_xor_sync(ALLM, a3, m);
    }

    // ---- BN (batch stats local) + ReLU -> smem ----
    a0 += bias; a1 += bias; a2 += bias; a3 += bias;
    const float mean = 0.25f * (a0 + a1 + a2 + a3);
    const float d0 = a0 - mean, d1 = a1 - mean, d2 = a2 - mean, d3 = a3 - mean;
    const float var = 0.25f * (d0*d0 + d1*d1 + d2*d2 + d3*d3);
    const float scl = gam * rsqrtf(var + EPSV);

    if (s < 4) {
        const float d = (s == 0) ? d0 : (s == 1) ? d1 : (s == 2) ? d2 : d3;
        r_s[s][jloc] = fmaxf(d * scl + bet, 0.f);
    }
    __syncthreads();

    // ---- phase2 partial: (o2, b2i), 32-MAC over this block's channels ----
    const float4* rrow = (const float4*)r_s[b2i];
    float acc = 0.f;
    #pragma unroll
    for (int i = 0; i < 8; ++i) {
        const float4 w = wv2[i];
        const float4 r = rrow[i];
        acc += r.x*w.x + r.y*w.y + r.z*w.z + r.w*w.w;
    }
    g_part[((long long)(k * 8 + ch8)) * 256 + b2i * 64 + o2] = acc;

    // ---- arrive (grid.sync pattern: bar + acq_rel atomic, NO L1 flush) ----
    __syncthreads();
    if (t == 0)
        last_s = (atom_add_acqrel(&g_cnt[k], 1) == 7) ? 1 : 0;
    __syncthreads();

    // ---- last arriving block of this level reduces the 8 partials ----
    if (last_s) {
        const float* pk = g_part + (long long)k * 8 * 256;
        float sum = 0.f;
        #pragma unroll
        for (int c = 0; c < 8; ++c)
            sum += pk[c * 256 + t];
        out[k * 256 + t] = sum + bias2;
        if (t == 0)
            g_cnt[k] = 0;                  // reset for next graph replay
    }
}

extern "C" void kernel_launch(void* const* d_in, const int* in_sizes, int n_in,
                              void* d_out, int out_size)
{
    (void)in_sizes; (void)n_in; (void)out_size;
    const float* x0    = (const float*)d_in[0];
    const float* x1    = (const float*)d_in[1];
    const float* x2    = (const float*)d_in[2];
    const float* x3    = (const float*)d_in[3];
    const float* x4    = (const float*)d_in[4];
    const int*   p     = (const int*)  d_in[5];
    const float* w1    = (const float*)d_in[6];
    const float* b1    = (const float*)d_in[7];
    const float* gamma = (const float*)d_in[8];
    const float* beta  = (const float*)d_in[9];
    const float* w2    = (const float*)d_in[10];
    const float* b2v   = (const float*)d_in[11];
    float* out = (float*)d_out;

    proj_fused_kernel<<<40, 256>>>(x0, x1, x2, x3, x4, p,
                                   w1, b1, gamma, beta, w2, b2v, out);
}